// round 7
// baseline (speedup 1.0000x reference)
#include <cuda_runtime.h>
#include <cuda_bf16.h>
#include <cstdint>

#define NTOK 16384
#define DMODEL 2048
#define NEXP 64
#define CAP 512

#define BM 128
#define BN 64
#define BK 32

// ---------------------------------------------------------------------------
// GEMM: logits = x @ W^T + b. BIT-EXACT vs reference (established R3):
// split-K=4 contiguous segments (SEG=512 along K), sequential fma per segment
// (ascending k), sequential partial fold, then + b.
// ---------------------------------------------------------------------------
__global__ __launch_bounds__(256, 1)
void router_gemm_kernel(const float* __restrict__ x,
                        const float* __restrict__ W,
                        const float* __restrict__ b,
                        float* __restrict__ logits)
{
    __shared__ float As[BK][BM + 4];
    __shared__ float Bs[BK][BN + 4];

    const int tid = threadIdx.x;
    const int tx = tid & 15;
    const int ty = tid >> 4;
    const int row0 = blockIdx.x * BM;

    float acc[8][4];
    float tot[8][4];
#pragma unroll
    for (int i = 0; i < 8; i++)
#pragma unroll
        for (int j = 0; j < 4; j++) { acc[i][j] = 0.0f; tot[i][j] = 0.0f; }

    const int NKT = DMODEL / BK;
    const int SEG = NKT / 4;

    for (int kt = 0; kt < NKT; kt++) {
        const int k0 = kt * BK;
#pragma unroll
        for (int r = 0; r < 4; r++) {
            int f = tid + r * 256;
            int m = f >> 3;
            int kq = f & 7;
            float4 v = *reinterpret_cast<const float4*>(
                x + (size_t)(row0 + m) * DMODEL + k0 + kq * 4);
            As[kq * 4 + 0][m] = v.x;
            As[kq * 4 + 1][m] = v.y;
            As[kq * 4 + 2][m] = v.z;
            As[kq * 4 + 3][m] = v.w;
        }
#pragma unroll
        for (int r = 0; r < 2; r++) {
            int f = tid + r * 256;
            int n = f >> 3;
            int kq = f & 7;
            float4 v = *reinterpret_cast<const float4*>(
                W + (size_t)n * DMODEL + k0 + kq * 4);
            Bs[kq * 4 + 0][n] = v.x;
            Bs[kq * 4 + 1][n] = v.y;
            Bs[kq * 4 + 2][n] = v.z;
            Bs[kq * 4 + 3][n] = v.w;
        }
        __syncthreads();

#pragma unroll
        for (int k = 0; k < BK; k++) {
            float4 a0 = *reinterpret_cast<const float4*>(&As[k][ty * 8]);
            float4 a1 = *reinterpret_cast<const float4*>(&As[k][ty * 8 + 4]);
            float4 w0 = *reinterpret_cast<const float4*>(&Bs[k][tx * 4]);
            const float a[8] = {a0.x, a0.y, a0.z, a0.w, a1.x, a1.y, a1.z, a1.w};
            const float w[4] = {w0.x, w0.y, w0.z, w0.w};
#pragma unroll
            for (int i = 0; i < 8; i++)
#pragma unroll
                for (int j = 0; j < 4; j++)
                    acc[i][j] = fmaf(a[i], w[j], acc[i][j]);
        }
        __syncthreads();

        if ((kt + 1) % SEG == 0) {
#pragma unroll
            for (int i = 0; i < 8; i++)
#pragma unroll
                for (int j = 0; j < 4; j++) {
                    tot[i][j] = tot[i][j] + acc[i][j];
                    acc[i][j] = 0.0f;
                }
        }
    }

    const int col = tx * 4;
    float4 bb = *reinterpret_cast<const float4*>(b + col);
#pragma unroll
    for (int i = 0; i < 8; i++) {
        int row = row0 + ty * 8 + i;
        float4 o;
        o.x = tot[i][0] + bb.x;
        o.y = tot[i][1] + bb.y;
        o.z = tot[i][2] + bb.z;
        o.w = tot[i][3] + bb.w;
        *reinterpret_cast<float4*>(logits + (size_t)row * NEXP + col) = o;
    }
}

// ---------------------------------------------------------------------------
// exp candidate 1: glibc/ARM optimized-routines expf (double-based, N=32).
// All intermediate math in IEEE double with explicit intrinsics (FMA where
// aarch64 -ffp-contract=fast would fuse). Valid for x in [-87, 0] (our range).
// ---------------------------------------------------------------------------
__device__ __constant__ unsigned long long EXP2F_TAB[32] = {
    0x3ff0000000000000ULL, 0x3fefd9b0d3158574ULL, 0x3fefb5586cf9890fULL, 0x3fef9301d0125b51ULL,
    0x3fef72b83c7d517bULL, 0x3fef54873168b9aaULL, 0x3fef387a6e756238ULL, 0x3fef1e9df51fdee1ULL,
    0x3fef06fe0a31b715ULL, 0x3feef1a7373aa9cbULL, 0x3feedea64c123422ULL, 0x3feece086061892dULL,
    0x3feebfdad5362a27ULL, 0x3feeb42b569d4f82ULL, 0x3feeab07dd485429ULL, 0x3feea47eb03a5585ULL,
    0x3feea09e667f3bcdULL, 0x3fee9f75e8ec5f74ULL, 0x3feea11473eb0187ULL, 0x3feea589994cce13ULL,
    0x3feeace5422aa0dbULL, 0x3feeb737b0cdc5e5ULL, 0x3feec49182a3f090ULL, 0x3feed503b23e255dULL,
    0x3feee89f995ad3adULL, 0x3feeff76f2fb5e47ULL, 0x3fef199bdd85529cULL, 0x3fef3720dcef9069ULL,
    0x3fef5818dcfba487ULL, 0x3fef7c97337b9b5fULL, 0x3fefa4afa2a490daULL, 0x3fefd0765b6e4540ULL
};

__device__ __forceinline__ float expf_glibc(float x) {
    const double InvLn2N = 0x1.71547652b82fep+0 * 32.0;
    const double Shift   = 0x1.8p+52;
    const double C0 = 0x1.c6af84b912394p-5 / 32.0 / 32.0 / 32.0;
    const double C1 = 0x1.ebfce50fac4f3p-3 / 32.0 / 32.0;
    const double C2 = 0x1.62e42ff0c52d6p-1 / 32.0;

    double xd = (double)x;
    double z  = __dmul_rn(InvLn2N, xd);
    double kd = __dadd_rn(z, Shift);
    unsigned long long ki = __double_as_longlong(kd);
    kd = __dsub_rn(kd, Shift);
    double r = __dsub_rn(z, kd);
    unsigned long long t = EXP2F_TAB[ki & 31] + (ki << 47);
    double s  = __longlong_as_double(t);
    double zz = __fma_rn(C0, r, C1);
    double r2 = __dmul_rn(r, r);
    double y  = __fma_rn(C2, r, 1.0);
    y = __fma_rn(zz, r2, y);
    y = __dmul_rn(y, s);
    return (float)y;
}

// ---------------------------------------------------------------------------
// exp candidate 2: XLA:CPU / Eigen Cephes polynomial expf, float, NO fma
// (explicit __fmul_rn/__fadd_rn so nvcc cannot contract).
// ---------------------------------------------------------------------------
__device__ __forceinline__ float expf_cephes(float x) {
    const float LOG2EF = 1.44269504088896341f;
    const float Ca = 0.693359375f;
    const float Cb = -2.12194440e-4f;
    float fx = __fadd_rn(__fmul_rn(x, LOG2EF), 0.5f);
    fx = floorf(fx);
    float tmp = __fmul_rn(fx, Ca);
    float zc  = __fmul_rn(fx, Cb);
    float xx  = __fsub_rn(x, tmp);
    xx = __fsub_rn(xx, zc);
    float z2 = __fmul_rn(xx, xx);
    float y = 1.9875691500e-4f;
    y = __fadd_rn(__fmul_rn(y, xx), 1.3981999507e-3f);
    y = __fadd_rn(__fmul_rn(y, xx), 8.3334519073e-3f);
    y = __fadd_rn(__fmul_rn(y, xx), 4.1665795894e-2f);
    y = __fadd_rn(__fmul_rn(y, xx), 1.6666665459e-1f);
    y = __fadd_rn(__fmul_rn(y, xx), 5.0000001201e-1f);
    y = __fadd_rn(__fmul_rn(y, z2), xx);
    y = __fadd_rn(y, 1.0f);
    int n = (int)fx;
    float p2n = __int_as_float((n + 127) << 23);
    return __fmul_rn(y, p2n);
}

// ---------------------------------------------------------------------------
// Softmax(axis=0) + per-expert top-512. CPU-reference model:
//   denom = FULL SEQUENTIAL sum over tokens ascending (XLA:CPU reduce loop).
//   probs output (out1 oracle): expf_glibc.
//   top-k path (out2/out3):    expf_cephes.
// Sort by prob bits desc, ties -> ascending token index.
// ---------------------------------------------------------------------------
__device__ __forceinline__ float warp_max(float v) {
#pragma unroll
    for (int o = 16; o > 0; o >>= 1)
        v = fmaxf(v, __shfl_xor_sync(0xFFFFFFFFu, v, o));
    return v;
}

__global__ __launch_bounds__(1024, 1)
void softmax_topk_kernel(const float* __restrict__ logits,
                         float* __restrict__ probs,
                         float* __restrict__ eprobs,
                         float* __restrict__ eidx)
{
    // Dynamic SMEM: keys[16384] u64 (128KB) then vals[16384] f32 (64KB).
    extern __shared__ unsigned long long keys[];
    float* vals = (float*)(keys + NTOK);
    __shared__ float sred[32];
    __shared__ float sden[2];

    const int e = blockIdx.x;
    const int tid = threadIdx.x;
    const int lane = tid & 31;
    const int wid = tid >> 5;

    float lv[16];
    float mx = -3.4e38f;
#pragma unroll
    for (int i = 0; i < 16; i++) {
        int t = i * 1024 + tid;
        lv[i] = logits[(size_t)t * NEXP + e];
        mx = fmaxf(mx, lv[i]);
    }
    mx = warp_max(mx);
    if (lane == 0) sred[wid] = mx;
    __syncthreads();
    if (wid == 0) {
        float v = warp_max(sred[lane]);
        if (lane == 0) sred[0] = v;
    }
    __syncthreads();
    mx = sred[0];
    __syncthreads();

    // ---- Slot 1: glibc exp + full-seq denom -> probs (out1 oracle) ----
    float pv[16];
#pragma unroll
    for (int i = 0; i < 16; i++) {
        int t = i * 1024 + tid;
        pv[i] = expf_glibc(__fsub_rn(lv[i], mx));
        vals[t] = pv[i];
    }
    __syncthreads();
    if (tid == 0) {
        float a = 0.0f;
        for (int t = 0; t < NTOK; t++) a = __fadd_rn(a, vals[t]);
        sden[0] = a;
    }
    __syncthreads();
    const float dG = sden[0];
#pragma unroll
    for (int i = 0; i < 16; i++) {
        int t = i * 1024 + tid;
        probs[(size_t)t * NEXP + e] = pv[i] / dG;
    }
    __syncthreads();

    // ---- Slot 2: cephes exp + full-seq denom -> top-k (out2/out3) ----
#pragma unroll
    for (int i = 0; i < 16; i++) {
        int t = i * 1024 + tid;
        pv[i] = expf_cephes(__fsub_rn(lv[i], mx));
        vals[t] = pv[i];
    }
    __syncthreads();
    if (tid == 0) {
        float a = 0.0f;
        for (int t = 0; t < NTOK; t++) a = __fadd_rn(a, vals[t]);
        sden[1] = a;
    }
    __syncthreads();
    const float dC = sden[1];

#pragma unroll
    for (int i = 0; i < 16; i++) {
        int t = i * 1024 + tid;
        float pc = pv[i] / dC;
        unsigned int us = __float_as_uint(pc);    // pc > 0
        keys[t] = ((unsigned long long)(~us) << 32) | (unsigned int)t;
    }
    __syncthreads();

    // Bitonic sort ascending on (~p_bits, index).
    const int n = NTOK;
    for (int k = 2; k <= n; k <<= 1) {
        for (int j = k >> 1; j > 0; j >>= 1) {
#pragma unroll 4
            for (int i = tid; i < n; i += 1024) {
                int ixj = i ^ j;
                if (ixj > i) {
                    unsigned long long a = keys[i];
                    unsigned long long c = keys[ixj];
                    bool up = ((i & k) == 0);
                    if ((a > c) == up) { keys[i] = c; keys[ixj] = a; }
                }
            }
            __syncthreads();
        }
    }

    if (tid < CAP) {
        unsigned long long key = keys[tid];
        unsigned int t = (unsigned int)(key & 0xFFFFFFFFull);
        unsigned int us = ~(unsigned int)(key >> 32);
        eprobs[(size_t)e * CAP + tid] = __uint_as_float(us);
        eidx[(size_t)e * CAP + tid] = (float)t;
    }
}

// ---------------------------------------------------------------------------
extern "C" void kernel_launch(void* const* d_in, const int* in_sizes, int n_in,
                              void* d_out, int out_size)
{
    const float* x = (const float*)d_in[0];
    const float* W = (const float*)d_in[1];
    const float* b = (const float*)d_in[2];

    float* out = (float*)d_out;
    float* logits = out;
    float* probs  = out + (size_t)NTOK * NEXP;
    float* eprobs = out + 2 * (size_t)NTOK * NEXP;
    float* eidx   = eprobs + (size_t)NEXP * CAP;

    router_gemm_kernel<<<NTOK / BM, 256>>>(x, W, b, logits);

    const int smem = NTOK * (int)sizeof(unsigned long long) + NTOK * (int)sizeof(float);
    cudaFuncSetAttribute(softmax_topk_kernel,
                         cudaFuncAttributeMaxDynamicSharedMemorySize, smem);
    softmax_topk_kernel<<<NEXP, 1024, smem>>>(logits, probs, eprobs, eidx);
}

// round 8
// speedup vs baseline: 1.1119x; 1.1119x over previous
#include <cuda_runtime.h>
#include <cstdint>
#include <cstring>

#define NTOK 16384
#define DMODEL 2048
#define NEXP 64
#define CAP 512

#define BM 128
#define BN 64
#define BK 32

// ---------------------------------------------------------------------------
// f32x2 packed helpers (per-lane IEEE RN, bit-identical to scalar fmaf/fadd).
// ---------------------------------------------------------------------------
__device__ __forceinline__ unsigned long long pack_dup(float w) {
    float2 f = make_float2(w, w);
    unsigned long long r;
    memcpy(&r, &f, 8);
    return r;
}
__device__ __forceinline__ float lo32(unsigned long long v) {
    return __uint_as_float((unsigned int)v);
}
__device__ __forceinline__ float hi32(unsigned long long v) {
    return __uint_as_float((unsigned int)(v >> 32));
}
__device__ __forceinline__ void fma2(unsigned long long& d,
                                     unsigned long long a, unsigned long long b) {
    asm("fma.rn.f32x2 %0, %1, %2, %3;" : "=l"(d) : "l"(a), "l"(b), "l"(d));
}
__device__ __forceinline__ unsigned long long add2(unsigned long long a,
                                                   unsigned long long b) {
    unsigned long long d;
    asm("add.rn.f32x2 %0, %1, %2;" : "=l"(d) : "l"(a), "l"(b));
    return d;
}

// ---------------------------------------------------------------------------
// GEMM: logits = x @ W^T + b. BIT-EXACT vs reference (R3): split-K=4
// contiguous segments, sequential fma per segment (ascending k), sequential
// partial fold, then + b. f32x2 packs M-row pairs; per-element op order is
// unchanged (packed lanes are independent IEEE RN FMAs).
// 128 threads: each computes 8 rows (4 pairs) x 8 cols.
// ---------------------------------------------------------------------------
__global__ __launch_bounds__(128, 1)
void router_gemm_kernel(const float* __restrict__ x,
                        const float* __restrict__ W,
                        const float* __restrict__ b,
                        float* __restrict__ logits)
{
    __shared__ __align__(16) float As[BK][BM + 4];   // [k][m]
    __shared__ __align__(16) float Bs[BK][BN + 4];   // [k][n]

    const int tid = threadIdx.x;     // 0..127
    const int tx = tid & 7;          // 8 n-groups of 8 cols
    const int ty = tid >> 3;         // 0..15, 8 rows each
    const int row0 = blockIdx.x * BM;

    unsigned long long acc2[4][8];   // [m-pair][n], lo = even row
    unsigned long long tot2[4][8];
#pragma unroll
    for (int p = 0; p < 4; p++)
#pragma unroll
        for (int j = 0; j < 8; j++) { acc2[p][j] = 0ull; tot2[p][j] = 0ull; }

    const int NKT = DMODEL / BK;   // 64
    const int SEG = NKT / 4;       // 16

    for (int kt = 0; kt < NKT; kt++) {
        const int k0 = kt * BK;

        // A tile: 1024 float4 / 128 threads = 8 each. Layout [k][m].
#pragma unroll
        for (int r = 0; r < 8; r++) {
            int f = tid + r * 128;
            int m = f >> 3;
            int kq = f & 7;
            float4 v = *reinterpret_cast<const float4*>(
                x + (size_t)(row0 + m) * DMODEL + k0 + kq * 4);
            As[kq * 4 + 0][m] = v.x;
            As[kq * 4 + 1][m] = v.y;
            As[kq * 4 + 2][m] = v.z;
            As[kq * 4 + 3][m] = v.w;
        }
        // B tile: 512 float4 / 128 threads = 4 each.
#pragma unroll
        for (int r = 0; r < 4; r++) {
            int f = tid + r * 128;
            int n = f >> 3;
            int kq = f & 7;
            float4 v = *reinterpret_cast<const float4*>(
                W + (size_t)n * DMODEL + k0 + kq * 4);
            Bs[kq * 4 + 0][n] = v.x;
            Bs[kq * 4 + 1][n] = v.y;
            Bs[kq * 4 + 2][n] = v.z;
            Bs[kq * 4 + 3][n] = v.w;
        }
        __syncthreads();

#pragma unroll 8
        for (int k = 0; k < BK; k++) {
            const unsigned long long* ap =
                reinterpret_cast<const unsigned long long*>(&As[k][ty * 8]);
            unsigned long long a0 = ap[0], a1 = ap[1], a2 = ap[2], a3 = ap[3];
            float4 wv0 = *reinterpret_cast<const float4*>(&Bs[k][tx * 8]);
            float4 wv1 = *reinterpret_cast<const float4*>(&Bs[k][tx * 8 + 4]);
            unsigned long long w[8];
            w[0] = pack_dup(wv0.x); w[1] = pack_dup(wv0.y);
            w[2] = pack_dup(wv0.z); w[3] = pack_dup(wv0.w);
            w[4] = pack_dup(wv1.x); w[5] = pack_dup(wv1.y);
            w[6] = pack_dup(wv1.z); w[7] = pack_dup(wv1.w);
#pragma unroll
            for (int j = 0; j < 8; j++) {
                fma2(acc2[0][j], a0, w[j]);
                fma2(acc2[1][j], a1, w[j]);
                fma2(acc2[2][j], a2, w[j]);
                fma2(acc2[3][j], a3, w[j]);
            }
        }
        __syncthreads();

        if ((kt + 1) % SEG == 0) {
#pragma unroll
            for (int p = 0; p < 4; p++)
#pragma unroll
                for (int j = 0; j < 8; j++) {
                    tot2[p][j] = add2(tot2[p][j], acc2[p][j]);
                    acc2[p][j] = 0ull;
                }
        }
    }

    const int col = tx * 8;
    float4 bb0 = *reinterpret_cast<const float4*>(b + col);
    float4 bb1 = *reinterpret_cast<const float4*>(b + col + 4);
    const float bbs[8] = {bb0.x, bb0.y, bb0.z, bb0.w, bb1.x, bb1.y, bb1.z, bb1.w};

#pragma unroll
    for (int p = 0; p < 4; p++) {
        int row_e = row0 + ty * 8 + 2 * p;
        float oe[8], oo[8];
#pragma unroll
        for (int j = 0; j < 8; j++) {
            oe[j] = lo32(tot2[p][j]) + bbs[j];
            oo[j] = hi32(tot2[p][j]) + bbs[j];
        }
        float* pe = logits + (size_t)row_e * NEXP + col;
        float* po = logits + (size_t)(row_e + 1) * NEXP + col;
        *reinterpret_cast<float4*>(pe)     = make_float4(oe[0], oe[1], oe[2], oe[3]);
        *reinterpret_cast<float4*>(pe + 4) = make_float4(oe[4], oe[5], oe[6], oe[7]);
        *reinterpret_cast<float4*>(po)     = make_float4(oo[0], oo[1], oo[2], oo[3]);
        *reinterpret_cast<float4*>(po + 4) = make_float4(oo[4], oo[5], oo[6], oo[7]);
    }
}

// ---------------------------------------------------------------------------
// Cephes expf (float, no fma) — established bit-match for the reference exp.
// ---------------------------------------------------------------------------
__device__ __forceinline__ float expf_cephes(float x) {
    const float LOG2EF = 1.44269504088896341f;
    const float Ca = 0.693359375f;
    const float Cb = -2.12194440e-4f;
    float fx = __fadd_rn(__fmul_rn(x, LOG2EF), 0.5f);
    fx = floorf(fx);
    float tmp = __fmul_rn(fx, Ca);
    float zc  = __fmul_rn(fx, Cb);
    float xx  = __fsub_rn(x, tmp);
    xx = __fsub_rn(xx, zc);
    float z2 = __fmul_rn(xx, xx);
    float y = 1.9875691500e-4f;
    y = __fadd_rn(__fmul_rn(y, xx), 1.3981999507e-3f);
    y = __fadd_rn(__fmul_rn(y, xx), 8.3334519073e-3f);
    y = __fadd_rn(__fmul_rn(y, xx), 4.1665795894e-2f);
    y = __fadd_rn(__fmul_rn(y, xx), 1.6666665459e-1f);
    y = __fadd_rn(__fmul_rn(y, xx), 5.0000001201e-1f);
    y = __fadd_rn(__fmul_rn(y, z2), xx);
    y = __fadd_rn(y, 1.0f);
    int n = (int)fx;
    float p2n = __int_as_float((n + 127) << 23);
    return __fmul_rn(y, p2n);
}

__device__ __forceinline__ float warp_max(float v) {
#pragma unroll
    for (int o = 16; o > 0; o >>= 1)
        v = fmaxf(v, __shfl_xor_sync(0xFFFFFFFFu, v, o));
    return v;
}

// ---------------------------------------------------------------------------
// Softmax(axis=0) + per-expert top-512.
// Numeric recipe (frozen from the R7 pass): cephes exp, full-sequential
// fp32 denominator (token-ascending), probs = pv / denom, keys = (~prob_bits,
// token) sorted ascending => top-512 = 512 smallest keys, ties -> lowest idx.
// Top-512 found by exact 64-bit MSB bisection on register-resident keys,
// then a 512-key bitonic sort. No 16384-wide sort.
// ---------------------------------------------------------------------------
__global__ __launch_bounds__(1024, 1)
void softmax_topk_kernel(const float* __restrict__ logits,
                         float* __restrict__ probs,
                         float* __restrict__ eprobs,
                         float* __restrict__ eidx)
{
    extern __shared__ float vals[];            // 16384 f32 = 64KB (token order)
    __shared__ float sred[32];
    __shared__ float sden;
    __shared__ int swcnt[32];
    __shared__ int sct;
    __shared__ int sgather;
    __shared__ unsigned long long sel[CAP];

    const int e = blockIdx.x;
    const int tid = threadIdx.x;
    const int lane = tid & 31;
    const int wid = tid >> 5;

    // ---- block max (order-independent) ----
    float lv[16];
    float mx = -3.4e38f;
#pragma unroll
    for (int i = 0; i < 16; i++) {
        int t = i * 1024 + tid;
        lv[i] = logits[(size_t)t * NEXP + e];
        mx = fmaxf(mx, lv[i]);
    }
    mx = warp_max(mx);
    if (lane == 0) sred[wid] = mx;
    __syncthreads();
    if (wid == 0) {
        float v = warp_max(sred[lane]);
        if (lane == 0) sred[0] = v;
    }
    __syncthreads();
    mx = sred[0];
    __syncthreads();

    // ---- exp (cephes) ----
    float pv[16];
#pragma unroll
    for (int i = 0; i < 16; i++) {
        int t = i * 1024 + tid;
        pv[i] = expf_cephes(__fsub_rn(lv[i], mx));
        vals[t] = pv[i];
    }
    __syncthreads();

    // ---- EXACT sequential denominator (token-ascending, fp32) ----
    if (tid == 0) {
        float a = 0.0f;
        for (int t = 0; t < NTOK; t++) a = __fadd_rn(a, vals[t]);
        sden = a;
    }
    __syncthreads();
    const float dC = sden;

    // ---- probs + key high-words (kept in registers) ----
    unsigned int kh[16];
#pragma unroll
    for (int i = 0; i < 16; i++) {
        int t = i * 1024 + tid;
        float pc = pv[i] / dC;                  // true IEEE division
        probs[(size_t)t * NEXP + e] = pc;
        kh[i] = ~__float_as_uint(pc);           // ascending-key order = prob desc
    }

    // ---- 64-bit MSB bisection: find the 512th-smallest key P ----
    unsigned long long P = 0ull;
    for (int bi = 63; bi >= 0; bi--) {
        unsigned long long T = P | (1ull << bi);
        int c = 0;
#pragma unroll
        for (int i = 0; i < 16; i++) {
            unsigned long long key =
                ((unsigned long long)kh[i] << 32) | (unsigned int)(i * 1024 + tid);
            c += (key < T) ? 1 : 0;
        }
        c = __reduce_add_sync(0xFFFFFFFFu, c);
        if (lane == 0) swcnt[wid] = c;
        __syncthreads();
        if (wid == 0) {
            int v = __reduce_add_sync(0xFFFFFFFFu, swcnt[lane]);
            if (lane == 0) sct = v;
        }
        __syncthreads();
        if (sct < CAP) P = T;   // uniform decision across block
    }

    // ---- gather the 512 keys <= P (exactly CAP by construction) ----
    if (tid == 0) sgather = 0;
    __syncthreads();
#pragma unroll
    for (int i = 0; i < 16; i++) {
        unsigned long long key =
            ((unsigned long long)kh[i] << 32) | (unsigned int)(i * 1024 + tid);
        if (key <= P) {
            int pos = atomicAdd(&sgather, 1);
            sel[pos] = key;
        }
    }
    __syncthreads();

    // ---- bitonic sort of 512 keys ascending ----
    for (int k2 = 2; k2 <= CAP; k2 <<= 1) {
        for (int j = k2 >> 1; j > 0; j >>= 1) {
            if (tid < CAP) {
                int i = tid;
                int ixj = i ^ j;
                if (ixj > i) {
                    unsigned long long a = sel[i];
                    unsigned long long c = sel[ixj];
                    bool up = ((i & k2) == 0);
                    if ((a > c) == up) { sel[i] = c; sel[ixj] = a; }
                }
            }
            __syncthreads();
        }
    }

    if (tid < CAP) {
        unsigned long long key = sel[tid];
        unsigned int t = (unsigned int)(key & 0xFFFFFFFFull);
        unsigned int us = ~(unsigned int)(key >> 32);
        eprobs[(size_t)e * CAP + tid] = __uint_as_float(us);
        eidx[(size_t)e * CAP + tid] = (float)t;
    }
}

// ---------------------------------------------------------------------------
// kernel_launch. Output layout (f32 concat):
//   [0, N*E) logits | [N*E, 2NE) probs | [2NE, +E*C) expert_probs | [+E*C] expert_indices
// ---------------------------------------------------------------------------
extern "C" void kernel_launch(void* const* d_in, const int* in_sizes, int n_in,
                              void* d_out, int out_size)
{
    const float* x = (const float*)d_in[0];
    const float* W = (const float*)d_in[1];
    const float* b = (const float*)d_in[2];

    float* out = (float*)d_out;
    float* logits = out;
    float* probs  = out + (size_t)NTOK * NEXP;
    float* eprobs = out + 2 * (size_t)NTOK * NEXP;
    float* eidx   = eprobs + (size_t)NEXP * CAP;

    router_gemm_kernel<<<NTOK / BM, 128>>>(x, W, b, logits);

    const int smem = NTOK * (int)sizeof(float);   // 64KB
    cudaFuncSetAttribute(softmax_topk_kernel,
                         cudaFuncAttributeMaxDynamicSharedMemorySize, smem);
    softmax_topk_kernel<<<NEXP, 1024, smem>>>(logits, probs, eprobs, eidx);
}

// round 9
// speedup vs baseline: 1.6093x; 1.4474x over previous
#include <cuda_runtime.h>
#include <cstdint>
#include <cstring>

#define NTOK 16384
#define DMODEL 2048
#define NEXP 64
#define CAP 512

#define BM 128
#define BN 64
#define BK 32

// Transposed logits scratch [e][t] for coalesced softmax loads (device global:
// allocation-free rule).
__device__ float g_logitsT[(size_t)NEXP * NTOK];

// ---------------------------------------------------------------------------
// f32x2 helpers (per-lane IEEE RN, bit-identical to scalar fmaf/fadd).
// ---------------------------------------------------------------------------
__device__ __forceinline__ unsigned long long pack_dup(float w) {
    float2 f = make_float2(w, w);
    unsigned long long r;
    memcpy(&r, &f, 8);
    return r;
}
__device__ __forceinline__ float lo32(unsigned long long v) {
    return __uint_as_float((unsigned int)v);
}
__device__ __forceinline__ float hi32(unsigned long long v) {
    return __uint_as_float((unsigned int)(v >> 32));
}
__device__ __forceinline__ void fma2(unsigned long long& d,
                                     unsigned long long a, unsigned long long b) {
    asm("fma.rn.f32x2 %0, %1, %2, %3;" : "=l"(d) : "l"(a), "l"(b), "l"(d));
}
__device__ __forceinline__ unsigned long long add2(unsigned long long a,
                                                   unsigned long long b) {
    unsigned long long d;
    asm("add.rn.f32x2 %0, %1, %2;" : "=l"(d) : "l"(a), "l"(b));
    return d;
}

// ---------------------------------------------------------------------------
// GEMM: logits = x @ W^T + b. BIT-EXACT vs reference: split-K=4 contiguous
// segments, sequential fma per segment (ascending k), sequential fold, + b.
// f32x2 packs COLUMN pairs (B loads naturally paired). 256 threads,
// per-thread 4 rows x 8 cols. Double-buffered SMEM, register-staged prefetch.
// Epilogue also writes transposed logits to g_logitsT.
// ---------------------------------------------------------------------------
__global__ __launch_bounds__(256, 1)
void router_gemm_kernel(const float* __restrict__ x,
                        const float* __restrict__ W,
                        const float* __restrict__ b,
                        float* __restrict__ logits,
                        float* __restrict__ logitsT)
{
    __shared__ __align__(16) float As[2][BK][BM + 4];
    __shared__ __align__(16) float Bs[2][BK][BN + 4];

    const int tid = threadIdx.x;     // 0..255
    const int tx = tid & 7;          // 8 col-groups of 8
    const int ty = tid >> 3;         // 0..31, 4 rows each
    const int row0 = blockIdx.x * BM;

    unsigned long long acc2[4][4];   // [row][colpair], lo = even col
    unsigned long long tot2[4][4];
#pragma unroll
    for (int r = 0; r < 4; r++)
#pragma unroll
        for (int jp = 0; jp < 4; jp++) { acc2[r][jp] = 0ull; tot2[r][jp] = 0ull; }

    float4 ra[4];
    float4 rb[2];

    auto load_tile = [&](int kt) {
        const int k0 = kt * BK;
#pragma unroll
        for (int r = 0; r < 4; r++) {
            int f = tid + r * 256;
            int m = f >> 3;
            int kq = f & 7;
            ra[r] = *reinterpret_cast<const float4*>(
                x + (size_t)(row0 + m) * DMODEL + k0 + kq * 4);
        }
#pragma unroll
        for (int r = 0; r < 2; r++) {
            int f = tid + r * 256;
            int n = f >> 3;
            int kq = f & 7;
            rb[r] = *reinterpret_cast<const float4*>(
                W + (size_t)n * DMODEL + k0 + kq * 4);
        }
    };
    auto store_tile = [&](int buf) {
#pragma unroll
        for (int r = 0; r < 4; r++) {
            int f = tid + r * 256;
            int m = f >> 3;
            int kq = f & 7;
            As[buf][kq * 4 + 0][m] = ra[r].x;
            As[buf][kq * 4 + 1][m] = ra[r].y;
            As[buf][kq * 4 + 2][m] = ra[r].z;
            As[buf][kq * 4 + 3][m] = ra[r].w;
        }
#pragma unroll
        for (int r = 0; r < 2; r++) {
            int f = tid + r * 256;
            int n = f >> 3;
            int kq = f & 7;
            Bs[buf][kq * 4 + 0][n] = rb[r].x;
            Bs[buf][kq * 4 + 1][n] = rb[r].y;
            Bs[buf][kq * 4 + 2][n] = rb[r].z;
            Bs[buf][kq * 4 + 3][n] = rb[r].w;
        }
    };

    const int NKT = DMODEL / BK;   // 64
    const int SEG = NKT / 4;       // 16

    load_tile(0);
    store_tile(0);
    __syncthreads();

    for (int kt = 0; kt < NKT; kt++) {
        const int cur = kt & 1;
        if (kt < NKT - 1) load_tile(kt + 1);

#pragma unroll
        for (int k = 0; k < BK; k++) {
            float4 av = *reinterpret_cast<const float4*>(&As[cur][k][ty * 4]);
            ulonglong2 w01 = *reinterpret_cast<const ulonglong2*>(&Bs[cur][k][tx * 8]);
            ulonglong2 w23 = *reinterpret_cast<const ulonglong2*>(&Bs[cur][k][tx * 8 + 4]);
            unsigned long long ad0 = pack_dup(av.x);
            unsigned long long ad1 = pack_dup(av.y);
            unsigned long long ad2 = pack_dup(av.z);
            unsigned long long ad3 = pack_dup(av.w);
            unsigned long long wp[4] = {w01.x, w01.y, w23.x, w23.y};
#pragma unroll
            for (int jp = 0; jp < 4; jp++) {
                fma2(acc2[0][jp], ad0, wp[jp]);
                fma2(acc2[1][jp], ad1, wp[jp]);
                fma2(acc2[2][jp], ad2, wp[jp]);
                fma2(acc2[3][jp], ad3, wp[jp]);
            }
        }

        if (kt < NKT - 1) {
            store_tile(cur ^ 1);
            __syncthreads();
        }

        if ((kt + 1) % SEG == 0) {
#pragma unroll
            for (int r = 0; r < 4; r++)
#pragma unroll
                for (int jp = 0; jp < 4; jp++) {
                    tot2[r][jp] = add2(tot2[r][jp], acc2[r][jp]);
                    acc2[r][jp] = 0ull;
                }
        }
    }

    const int col = tx * 8;
    float4 bb0 = *reinterpret_cast<const float4*>(b + col);
    float4 bb1 = *reinterpret_cast<const float4*>(b + col + 4);
    const float bbs[8] = {bb0.x, bb0.y, bb0.z, bb0.w, bb1.x, bb1.y, bb1.z, bb1.w};

#pragma unroll
    for (int r = 0; r < 4; r++) {
        int row = row0 + ty * 4 + r;
        float o[8];
#pragma unroll
        for (int jp = 0; jp < 4; jp++) {
            o[2 * jp]     = lo32(tot2[r][jp]) + bbs[2 * jp];
            o[2 * jp + 1] = hi32(tot2[r][jp]) + bbs[2 * jp + 1];
        }
        float* pr = logits + (size_t)row * NEXP + col;
        *reinterpret_cast<float4*>(pr)     = make_float4(o[0], o[1], o[2], o[3]);
        *reinterpret_cast<float4*>(pr + 4) = make_float4(o[4], o[5], o[6], o[7]);
#pragma unroll
        for (int j = 0; j < 8; j++)
            logitsT[(size_t)(col + j) * NTOK + row] = o[j];
    }
}

// ---------------------------------------------------------------------------
// Cephes expf (float, no fma) — established bit-match to reference exp.
// ---------------------------------------------------------------------------
__device__ __forceinline__ float expf_cephes(float x) {
    const float LOG2EF = 1.44269504088896341f;
    const float Ca = 0.693359375f;
    const float Cb = -2.12194440e-4f;
    float fx = __fadd_rn(__fmul_rn(x, LOG2EF), 0.5f);
    fx = floorf(fx);
    float tmp = __fmul_rn(fx, Ca);
    float zc  = __fmul_rn(fx, Cb);
    float xx  = __fsub_rn(x, tmp);
    xx = __fsub_rn(xx, zc);
    float z2 = __fmul_rn(xx, xx);
    float y = 1.9875691500e-4f;
    y = __fadd_rn(__fmul_rn(y, xx), 1.3981999507e-3f);
    y = __fadd_rn(__fmul_rn(y, xx), 8.3334519073e-3f);
    y = __fadd_rn(__fmul_rn(y, xx), 4.1665795894e-2f);
    y = __fadd_rn(__fmul_rn(y, xx), 1.6666665459e-1f);
    y = __fadd_rn(__fmul_rn(y, xx), 5.0000001201e-1f);
    y = __fadd_rn(__fmul_rn(y, z2), xx);
    y = __fadd_rn(y, 1.0f);
    int n = (int)fx;
    float p2n = __int_as_float((n + 127) << 23);
    return __fmul_rn(y, p2n);
}

__device__ __forceinline__ float warp_max(float v) {
#pragma unroll
    for (int o = 16; o > 0; o >>= 1)
        v = fmaxf(v, __shfl_xor_sync(0xFFFFFFFFu, v, o));
    return v;
}

// ---------------------------------------------------------------------------
// Softmax(axis=0) + per-expert top-512. Numeric recipe frozen (R7 pass):
// cephes exp, token-ascending full-sequential fp32 denom, pc = pv/denom,
// keys (~pc_bits, idx) ascending; top-512 = 512 smallest. Selection via
// 32-bit bisection on kh then 14-bit bisection on index among ties.
// ---------------------------------------------------------------------------
__global__ __launch_bounds__(1024, 1)
void softmax_topk_kernel(const float* __restrict__ logitsT,
                         float* __restrict__ probs,
                         float* __restrict__ eprobs,
                         float* __restrict__ eidx)
{
    extern __shared__ float vals[];            // 16384 f32, token order
    __shared__ float sredf[32];
    __shared__ float sden;
    __shared__ int swcnt[32];
    __shared__ int sct;
    __shared__ int sgather;
    __shared__ unsigned long long sel[CAP];

    const int e = blockIdx.x;
    const int tid = threadIdx.x;
    const int lane = tid & 31;
    const int wid = tid >> 5;
    const float* Lt = logitsT + (size_t)e * NTOK;

    // ---- coalesced loads: thread owns tokens [tid*16, tid*16+16) ----
    float lv[16];
    float mx = -3.4e38f;
#pragma unroll
    for (int c = 0; c < 4; c++) {
        float4 v = *reinterpret_cast<const float4*>(Lt + tid * 16 + c * 4);
        lv[c * 4 + 0] = v.x; lv[c * 4 + 1] = v.y;
        lv[c * 4 + 2] = v.z; lv[c * 4 + 3] = v.w;
    }
#pragma unroll
    for (int i = 0; i < 16; i++) mx = fmaxf(mx, lv[i]);
    mx = warp_max(mx);
    if (lane == 0) sredf[wid] = mx;
    __syncthreads();
    if (wid == 0) {
        float v = warp_max(sredf[lane]);
        if (lane == 0) sredf[0] = v;
    }
    __syncthreads();
    mx = sredf[0];
    __syncthreads();

    // ---- exp (cephes) ----
    float pv[16];
#pragma unroll
    for (int i = 0; i < 16; i++)
        pv[i] = expf_cephes(__fsub_rn(lv[i], mx));
#pragma unroll
    for (int c = 0; c < 4; c++)
        *reinterpret_cast<float4*>(vals + tid * 16 + c * 4) =
            make_float4(pv[c * 4], pv[c * 4 + 1], pv[c * 4 + 2], pv[c * 4 + 3]);
    __syncthreads();

    // ---- EXACT sequential denom, register-batched so LDS stays off the chain ----
    if (tid == 0) {
        float a = 0.0f;
        for (int t = 0; t < NTOK; t += 8) {
            float c0 = vals[t + 0], c1 = vals[t + 1], c2 = vals[t + 2], c3 = vals[t + 3];
            float c4 = vals[t + 4], c5 = vals[t + 5], c6 = vals[t + 6], c7 = vals[t + 7];
            a = __fadd_rn(a, c0); a = __fadd_rn(a, c1);
            a = __fadd_rn(a, c2); a = __fadd_rn(a, c3);
            a = __fadd_rn(a, c4); a = __fadd_rn(a, c5);
            a = __fadd_rn(a, c6); a = __fadd_rn(a, c7);
        }
        sden = a;
    }
    __syncthreads();
    const float dC = sden;

    // ---- probs + key high-words ----
    unsigned int kh[16];
#pragma unroll
    for (int i = 0; i < 16; i++) {
        int t = tid * 16 + i;
        float pc = pv[i] / dC;
        probs[(size_t)t * NEXP + e] = pc;
        kh[i] = ~__float_as_uint(pc);
    }

    // block add-reduce with broadcast
    auto block_count = [&](int c) -> int {
        c = __reduce_add_sync(0xFFFFFFFFu, c);
        if (lane == 0) swcnt[wid] = c;
        __syncthreads();
        if (wid == 0) {
            int v = __reduce_add_sync(0xFFFFFFFFu, swcnt[lane]);
            if (lane == 0) sct = v;
        }
        __syncthreads();
        return sct;
    };

    // ---- 32-bit bisection: P = kh-value of 512th smallest ----
    unsigned int P = 0u;
    for (int bi = 31; bi >= 0; bi--) {
        unsigned int T = P | (1u << bi);
        int c = 0;
#pragma unroll
        for (int i = 0; i < 16; i++) c += (kh[i] < T) ? 1 : 0;
        if (block_count(c) < CAP) P = T;
    }
    // count strictly below P
    int cl = 0;
#pragma unroll
    for (int i = 0; i < 16; i++) cl += (kh[i] < P) ? 1 : 0;
    const int c_less = block_count(cl);
    const int need = CAP - c_less;

    // ---- 14-bit bisection on index among ties (kh == P) ----
    unsigned int I = 0u;
    for (int bi = 13; bi >= 0; bi--) {
        unsigned int T = I | (1u << bi);
        int c = 0;
#pragma unroll
        for (int i = 0; i < 16; i++)
            c += (kh[i] == P && (unsigned int)(tid * 16 + i) < T) ? 1 : 0;
        if (block_count(c) < need) I = T;
    }

    // ---- gather exactly 512 ----
    if (tid == 0) sgather = 0;
    __syncthreads();
#pragma unroll
    for (int i = 0; i < 16; i++) {
        unsigned int idx = (unsigned int)(tid * 16 + i);
        if (kh[i] < P || (kh[i] == P && idx <= I)) {
            int pos = atomicAdd(&sgather, 1);
            sel[pos] = ((unsigned long long)kh[i] << 32) | idx;
        }
    }
    __syncthreads();

    // ---- bitonic sort 512 ascending ----
    for (int k2 = 2; k2 <= CAP; k2 <<= 1) {
        for (int j = k2 >> 1; j > 0; j >>= 1) {
            if (tid < CAP) {
                int i = tid;
                int ixj = i ^ j;
                if (ixj > i) {
                    unsigned long long a = sel[i];
                    unsigned long long c = sel[ixj];
                    bool up = ((i & k2) == 0);
                    if ((a > c) == up) { sel[i] = c; sel[ixj] = a; }
                }
            }
            __syncthreads();
        }
    }

    if (tid < CAP) {
        unsigned long long key = sel[tid];
        unsigned int t = (unsigned int)(key & 0xFFFFFFFFull);
        unsigned int us = ~(unsigned int)(key >> 32);
        eprobs[(size_t)e * CAP + tid] = __uint_as_float(us);
        eidx[(size_t)e * CAP + tid] = (float)t;
    }
}

// ---------------------------------------------------------------------------
extern "C" void kernel_launch(void* const* d_in, const int* in_sizes, int n_in,
                              void* d_out, int out_size)
{
    const float* x = (const float*)d_in[0];
    const float* W = (const float*)d_in[1];
    const float* b = (const float*)d_in[2];

    float* out = (float*)d_out;
    float* logits = out;
    float* probs  = out + (size_t)NTOK * NEXP;
    float* eprobs = out + 2 * (size_t)NTOK * NEXP;
    float* eidx   = eprobs + (size_t)NEXP * CAP;

    float* logitsT = nullptr;
    cudaGetSymbolAddress((void**)&logitsT, g_logitsT);

    router_gemm_kernel<<<NTOK / BM, 256>>>(x, W, b, logits, logitsT);

    const int smem = NTOK * (int)sizeof(float);   // 64 KB
    cudaFuncSetAttribute(softmax_topk_kernel,
                         cudaFuncAttributeMaxDynamicSharedMemorySize, smem);
    softmax_topk_kernel<<<NEXP, 1024, smem>>>(logitsT, probs, eprobs, eidx);
}